// round 3
// baseline (speedup 1.0000x reference)
#include <cuda_runtime.h>
#include <cstdint>

#define LOGZERO (-1e10f)

constexpr int BS    = 32;
constexpr int XMAX  = 1024;
constexpr int VOCAB = 1000;
constexpr int YMAX  = 128;
constexpr int L     = 2 * YMAX + 1;   // 257 path states
constexpr int ROW   = 132;            // padded compact-lp row (128 tokens + blank @128)
constexpr int NWARP = 9;              // 288 threads
constexpr int TM    = (YMAX + 1) * XMAX;  // 129*1024 per batch

// Scratch: compact gathered log-probs [BS][XMAX][ROW]  (~17.3 MB, static device global)
__device__ float g_lp[(size_t)BS * XMAX * ROW];

// ---------------------------------------------------------------------------
// Kernel 1: gather lp_path-relevant vocab entries into compact rows.
// slot k (k<128) = ys[b][k]; slot 128 = blank. Only frames t < src_size[b].
// ---------------------------------------------------------------------------
__global__ void gather_kernel(const float* __restrict__ ctc,
                              const int* __restrict__ ys,
                              const int* __restrict__ src_size,
                              const int* __restrict__ blank_p)
{
    int b   = blockIdx.y;
    int t0  = blockIdx.x * 8;
    int tid = threadIdx.x;                 // 0..127
    int src = src_size[b];
    if (t0 >= src) return;
    int tok   = ys[b * YMAX + tid];
    int blank = blank_p ? blank_p[0] : 0;
#pragma unroll
    for (int dt = 0; dt < 8; ++dt) {
        int t = t0 + dt;
        if (t < src) {
            const float* row  = ctc + ((size_t)(b * XMAX + t)) * VOCAB;
            float*       orow = g_lp + (size_t)(b * XMAX + t) * ROW;
            orow[tid] = row[tok];
            if (tid == 0) orow[128] = row[blank];
        }
    }
}

// ---------------------------------------------------------------------------
// Kernel 2: per-batch CTA does forward Viterbi DP, snapshot/score, backtrace
// (bp kept as 2 bit-planes in SMEM), collapse+csum, and trigger-mask writes.
// ---------------------------------------------------------------------------
__global__ __launch_bounds__(288, 1)
void dp_kernel(const int* __restrict__ src_size,
               const int* __restrict__ ys,
               const int* __restrict__ ylens,
               const int* __restrict__ blank_p,
               float* __restrict__ out)
{
    extern __shared__ unsigned char smraw[];
    float*    alphaA  = (float*)smraw;                        // 260 floats
    float*    alphaB  = alphaA + 260;                         // 260 floats
    unsigned* bpp     = (unsigned*)(alphaB + 260);            // XMAX*NWARP*2 words (73728 B)
    short*    path_sm = (short*)(bpp + XMAX * NWARP * 2);     // 258 shorts
    short*    sal     = path_sm + 258;                        // 1024 shorts (aligned tokens)
    short*    csum    = sal + XMAX;                           // 1024 shorts
    int*      partial = (int*)(csum + XMAX);                  // 256 ints
    __shared__ int sh_start;

    int b    = blockIdx.x;
    int tid  = threadIdx.x;
    int l    = tid;
    bool valid = (l < L);
    int src   = src_size[b];
    int yl    = ylens[b];
    int plen  = 2 * yl + 1;
    int blank = blank_p ? blank_p[0] : 0;
    int wid   = tid >> 5;
    int lane  = tid & 31;

    // init path tokens + alpha buffers (guard cells [0],[1] stay LOGZERO forever)
    if (tid < L)
        path_sm[tid] = (tid & 1) ? (short)ys[b * YMAX + ((tid - 1) >> 1)] : (short)blank;
    for (int i = tid; i < 260; i += blockDim.x) { alphaA[i] = LOGZERO; alphaB[i] = LOGZERO; }
    __syncthreads();
    if (tid == 0) alphaA[2] = 0.0f;   // alpha0: state 0 = 0, rest LOGZERO
    __syncthreads();

    int mytok = 0, prevtok = -1;
    if (valid) { mytok = path_sm[l]; if (l >= 2) prevtok = path_sm[l - 2]; }
    bool allow2  = valid && (l >= 2) && (mytok != prevtok);
    bool outside = valid && (l >= plen);
    int  slot    = valid ? ((l & 1) ? ((l - 1) >> 1) : 128) : 0;
    const float* lpbase = g_lp + (size_t)b * XMAX * ROW + slot;

    // register prefetch ring (depth 3) for the compact lp rows
    float lp0 = 0.f, lp1 = 0.f, lp2 = 0.f;
    if (valid) {
        lp0 = lpbase[0];
        if (1 < src) lp1 = lpbase[(size_t)ROW];
        if (2 < src) lp2 = lpbase[(size_t)2 * ROW];
    }

    float* cur = alphaA;
    float* nxt = alphaB;

    for (int t = 0; t < src; ++t) {
        float lp3 = 0.f;
        if (valid && (t + 3) < src) lp3 = lpbase[(size_t)(t + 3) * ROW];

        int   arg  = 0;
        float anew = 0.f;
        if (valid) {
            float a0 = cur[l + 2];
            float a1 = cur[l + 1];
            float a2 = allow2 ? cur[l] : LOGZERO;
            float best = a0; arg = 0;
            if (a1 > best) { best = a1; arg = 1; }   // first-max tie semantics (argmax)
            if (a2 > best) { best = a2; arg = 2; }
            anew = (outside ? LOGZERO : best) + lp0;
        }
        // pack back-pointers as two bit-planes per warp (2 bits/state total)
        unsigned p0 = __ballot_sync(0xffffffffu, arg & 1);
        unsigned p1 = __ballot_sync(0xffffffffu, (arg >> 1) & 1);
        if (lane == 0) {
            bpp[(t * NWARP + wid) * 2 + 0] = p0;
            bpp[(t * NWARP + wid) * 2 + 1] = p1;
        }
        if (valid) nxt[l + 2] = anew;
        __syncthreads();
        float* tmp = cur; cur = nxt; nxt = tmp;
        lp0 = lp1; lp1 = lp2; lp2 = lp3;
    }
    // cur == alpha_{src}

    if (tid == 0) {
        float s1 = cur[plen + 1];         // alpha_at[plen-1]
        float s2 = cur[plen];             // alpha_at[plen-2]
        float score = fmaxf(s1, s2);
        int   start = (s1 > s2) ? (plen - 1) : (plen - 2);
        sh_start = start;
        out[b] = score;
        out[32 + (size_t)BS * TM + b] = (float)(yl + 1);

        // backtrace (pointer chase entirely in SMEM)
        int s = 0;
        for (int t = XMAX - 1; t >= 0; --t) {
            if (t >= src)           s = 0;
            else if (t == src - 1)  s = start;
            else {
                int tt = t + 1;
                int w = s >> 5, bit = s & 31;
                unsigned q0 = bpp[(tt * NWARP + w) * 2 + 0];
                unsigned q1 = bpp[(tt * NWARP + w) * 2 + 1];
                int a = ((q0 >> bit) & 1) | (((q1 >> bit) & 1) << 1);
                s -= a;
            }
            sal[t] = path_sm[s];          // aligned token per frame
        }
    }
    __syncthreads();

    // collapse repeats + inclusive cumsum of (shift2 != blank)
    int f[4];
    if (tid < 256) {
        int base = tid * 4;
        int psum = 0;
#pragma unroll
        for (int k = 0; k < 4; ++k) {
            int e = base + k;
            int colprev = 0;
            if (e >= 1) {
                int a1 = sal[e - 1];
                int a2 = (e >= 2) ? sal[e - 2] : 0;
                colprev = (a1 == a2) ? 0 : a1;    // collapsed token at e-1
            }
            f[k] = (colprev != blank) ? 1 : 0;
            psum += f[k];
        }
        partial[tid] = psum;
    }
    __syncthreads();
    if (tid == 0) {
        int run = 0;
        for (int j = 0; j < 256; ++j) { int p = partial[j]; partial[j] = run; run += p; }
    }
    __syncthreads();
    if (tid < 256) {
        int run = partial[tid];
#pragma unroll
        for (int k = 0; k < 4; ++k) { run += f[k]; csum[tid * 4 + k] = (short)run; }
    }
    __syncthreads();

    // trigger_mask [ymax+1, xmax] for this batch, written as float 0/1
    float* tm_out = out + 32 + (size_t)b * TM;
    for (int idx = tid; idx < TM; idx += blockDim.x) {
        int y = idx >> 10;
        int t = idx & (XMAX - 1);
        int c = csum[t];
        bool in = (t < src);
        bool v;
        if (y == YMAX) v = ((c == YMAX) && in) || (t == src - 1);
        else           v = (c == y) && in;
        tm_out[idx] = v ? 1.0f : 0.0f;
    }
}

// ---------------------------------------------------------------------------
extern "C" void kernel_launch(void* const* d_in, const int* in_sizes, int n_in,
                              void* d_out, int out_size)
{
    const float* ctc      = (const float*)d_in[0];
    // d_in[1] = src_mask (bool) — derivable from src_size, intentionally unused
    const int*   src_size = (const int*)d_in[2];
    const int*   ys       = (const int*)d_in[3];
    const int*   ylens    = (const int*)d_in[4];
    const int*   blank_p  = (n_in >= 6) ? (const int*)d_in[5] : nullptr;
    float*       out      = (float*)d_out;

    dim3 gg(XMAX / 8, BS);
    gather_kernel<<<gg, 128>>>(ctc, ys, src_size, blank_p);

    size_t smbytes = 260 * 4 * 2                 // alpha double buffer
                   + (size_t)XMAX * NWARP * 2 * 4 // bp bit-planes
                   + 258 * 2                      // path tokens
                   + XMAX * 2                     // aligned tokens
                   + XMAX * 2                     // csum
                   + 256 * 4;                     // scan partials
    cudaFuncSetAttribute(dp_kernel, cudaFuncAttributeMaxDynamicSharedMemorySize, (int)smbytes);
    dp_kernel<<<BS, 288, smbytes>>>(src_size, ys, ylens, blank_p, out);
}

// round 4
// speedup vs baseline: 1.6482x; 1.6482x over previous
#include <cuda_runtime.h>
#include <cstdint>

#define LOGZERO  (-1e10f)
#define M2PEN    (-2e10f)   // additive penalty for disallowed skip transition

constexpr int BS    = 32;
constexpr int XMAX  = 1024;
constexpr int VOCAB = 1000;
constexpr int YMAX  = 128;
constexpr int L     = 2 * YMAX + 1;       // 257 path states
constexpr int CH    = 9;                  // states per lane (32*9 = 288 >= 257)
constexpr int PADL  = 12;                 // floats per lane in lp row (float4-aligned)
constexpr int ROWF  = 32 * PADL;          // 384 floats per (b,t) lp row
constexpr int TM    = (YMAX + 1) * XMAX;  // 129*1024 mask elems per batch

// state-ordered compact log-probs [BS][XMAX][ROWF] (~50 MB), zero-initialized
__device__ __align__(16) float g_lp[(size_t)BS * XMAX * ROWF];
// per-frame csum for the trigger mask [BS][XMAX]
__device__ __align__(16) int   g_csum[BS * XMAX];

// ---------------------------------------------------------------------------
// Kernel 1: gather. state s -> token: odd s = ys[(s-1)/2], even s = blank.
// Written at slot (s/9)*12 + s%9 so dp lane reads are float4-aligned.
// ---------------------------------------------------------------------------
__global__ void gather_kernel(const float* __restrict__ ctc,
                              const int* __restrict__ ys,
                              const int* __restrict__ src_size,
                              const int* __restrict__ blank_p)
{
    int b  = blockIdx.y;
    int t0 = blockIdx.x * 8;
    int s  = threadIdx.x;                  // 0..287
    int src = src_size[b];
    if (t0 >= src || s >= L) return;
    int blank = blank_p ? blank_p[0] : 0;
    int tok = (s & 1) ? ys[b * YMAX + ((s - 1) >> 1)] : blank;
    int q = s / CH, r = s - CH * q;
    float*       orow = g_lp + (size_t)(b * XMAX + t0) * ROWF + q * PADL + r;
    const float* irow = ctc  + (size_t)(b * XMAX + t0) * VOCAB + tok;
#pragma unroll
    for (int dt = 0; dt < 8; ++dt)
        if (t0 + dt < src)
            orow[(size_t)dt * ROWF] = irow[(size_t)dt * VOCAB];
}

// ---------------------------------------------------------------------------
// One DP time step: alpha entirely in registers, in-place (top-down k).
// ---------------------------------------------------------------------------
__device__ __forceinline__ void dp_step(float a[CH], const float lp[CH],
                                        const float m2add[CH], int lane,
                                        unsigned* __restrict__ bprow)
{
    float pa8 = __shfl_up_sync(0xffffffffu, a[8], 1);
    float pa7 = __shfl_up_sync(0xffffffffu, a[7], 1);
    if (lane == 0) { pa8 = LOGZERO; pa7 = LOGZERO; }
    unsigned packed = 0;
#pragma unroll
    for (int k = CH - 1; k >= 0; --k) {
        float m0  = a[k];
        float m1  = (k >= 1) ? a[k - 1] : pa8;
        float m2p = (k >= 2) ? a[k - 2] : ((k == 1) ? pa8 : pa7);
        float m2  = m2p + m2add[k];           // disallowed -> < any real alpha
        float b01 = fmaxf(m0, m1);
        float bst = fmaxf(b01, m2);
        unsigned arg = (m2 > b01) ? 2u : ((m1 > m0) ? 1u : 0u);  // first-max ties
        packed |= arg << (2 * k);
        a[k] = bst + lp[k];
    }
    bprow[lane] = packed;
}

__device__ __forceinline__ void lp_load(float lp[CH], const float* __restrict__ base, int t)
{
    const float4* p = (const float4*)(base + (size_t)t * ROWF);
    float4 v0 = p[0], v1 = p[1];
    lp[0] = v0.x; lp[1] = v0.y; lp[2] = v0.z; lp[3] = v0.w;
    lp[4] = v1.x; lp[5] = v1.y; lp[6] = v1.z; lp[7] = v1.w;
    lp[8] = base[(size_t)t * ROWF + 8];
}

// ---------------------------------------------------------------------------
// Kernel 2: one warp per batch. Forward Viterbi in registers, bp bits in SMEM,
// backtrace, collapse + csum (warp scan), score/ylens outputs.
// ---------------------------------------------------------------------------
__global__ __launch_bounds__(32)
void dp_kernel(const int* __restrict__ src_size,
               const int* __restrict__ ys,
               const int* __restrict__ ylens,
               const int* __restrict__ blank_p,
               float* __restrict__ out)
{
    extern __shared__ unsigned char smraw[];
    unsigned* bp        = (unsigned*)smraw;                  // 1024*32 u32 = 131072 B
    short*    path_sm   = (short*)(smraw + 131072);          // 260 shorts
    short*    sal       = path_sm + 260;                     // 1024 shorts (state per frame)
    float*    alpha_fin = (float*)(sal + 1024);              // 288 floats

    const int b    = blockIdx.x;
    const int lane = threadIdx.x;
    const int src  = src_size[b];
    const int yl   = ylens[b];
    const int plen = 2 * yl + 1;
    const int blank = blank_p ? blank_p[0] : 0;

    // path tokens
    for (int i = lane; i < L; i += 32)
        path_sm[i] = (i & 1) ? (short)ys[b * YMAX + ((i - 1) >> 1)] : (short)blank;
    __syncthreads();

    // per-lane constants
    float a[CH], m2add[CH];
#pragma unroll
    for (int k = 0; k < CH; ++k) {
        int s = lane * CH + k;
        bool allowed = (s >= 2) && (s < L) && (path_sm[s] != path_sm[s - 2]);
        m2add[k] = allowed ? 0.0f : M2PEN;
        a[k] = (s == 0) ? 0.0f : LOGZERO;    // alpha0
    }

    const float* lpbase = g_lp + (size_t)b * XMAX * ROWF + lane * PADL;

    // depth-3 lp prefetch ring (src >= 3 guaranteed by setup; clamp anyway)
    float lpA[CH], lpB[CH], lpC[CH];
    lp_load(lpA, lpbase, 0);
    lp_load(lpB, lpbase, min(1, src - 1));
    lp_load(lpC, lpbase, min(2, src - 1));

    int t = 0;
    for (; t + 3 <= src; t += 3) {
        dp_step(a, lpA, m2add, lane, bp + (size_t)t * 32);
        lp_load(lpA, lpbase, min(t + 3, src - 1));
        dp_step(a, lpB, m2add, lane, bp + (size_t)(t + 1) * 32);
        lp_load(lpB, lpbase, min(t + 4, src - 1));
        dp_step(a, lpC, m2add, lane, bp + (size_t)(t + 2) * 32);
        lp_load(lpC, lpbase, min(t + 5, src - 1));
    }
    if (t < src) { dp_step(a, lpA, m2add, lane, bp + (size_t)t * 32); ++t; }
    if (t < src) { dp_step(a, lpB, m2add, lane, bp + (size_t)t * 32); ++t; }

    // publish final alpha
#pragma unroll
    for (int k = 0; k < CH; ++k) alpha_fin[lane * CH + k] = a[k];
    __syncthreads();

    // score + backtrace (lane 0, all on-chip)
    if (lane == 0) {
        float s1 = alpha_fin[plen - 1];
        float s2 = alpha_fin[plen - 2];
        int start = (s1 > s2) ? (plen - 1) : (plen - 2);
        out[b] = fmaxf(s1, s2);
        out[32 + (size_t)BS * TM + b] = (float)(yl + 1);

        int s = 0;
        for (int tt = XMAX - 1; tt >= 0; --tt) {
            if (tt >= src)          s = 0;
            else if (tt == src - 1) s = start;
            else {
                int q = (s * 456) >> 12;            // s/9, exact for s<=287
                unsigned w = bp[(size_t)(tt + 1) * 32 + q];
                int r = s - CH * q;
                s -= (int)((w >> (2 * r)) & 3u);
            }
            sal[tt] = (short)s;
        }
    }
    __syncthreads();

    // collapse repeats + inclusive csum of (collapsed[e-1] != blank), warp scan
    const int base = lane * 32;
    int partial = 0;
    {
        int f;
        for (int j = 0; j < 32; ++j) {
            int e = base + j;
            int colprev = 0;
            if (e >= 1) {
                int a1 = path_sm[sal[e - 1]];
                int a2 = (e >= 2) ? path_sm[sal[e - 2]] : 0;
                colprev = (a1 == a2) ? 0 : a1;
            }
            f = (colprev != blank) ? 1 : 0;
            partial += f;
        }
    }
    int x = partial;
#pragma unroll
    for (int d = 1; d < 32; d <<= 1) {
        int y = __shfl_up_sync(0xffffffffu, x, d);
        if (lane >= d) x += y;
    }
    int run = x - partial;                   // exclusive prefix
    for (int j = 0; j < 32; ++j) {
        int e = base + j;
        int colprev = 0;
        if (e >= 1) {
            int a1 = path_sm[sal[e - 1]];
            int a2 = (e >= 2) ? path_sm[sal[e - 2]] : 0;
            colprev = (a1 == a2) ? 0 : a1;
        }
        run += (colprev != blank) ? 1 : 0;
        g_csum[b * XMAX + e] = run;
    }
}

// ---------------------------------------------------------------------------
// Kernel 3: trigger mask writes, full chip. One block per (b, y) row.
// ---------------------------------------------------------------------------
__global__ void mask_kernel(const int* __restrict__ src_size,
                            float* __restrict__ out)
{
    int b = blockIdx.x / (YMAX + 1);
    int y = blockIdx.x % (YMAX + 1);
    int src = src_size[b];
    int t0 = threadIdx.x * 4;
    const int4 c4 = *(const int4*)(g_csum + b * XMAX + t0);
    float4 v;
    {
        const int cs[4] = {c4.x, c4.y, c4.z, c4.w};
        float* vv = (float*)&v;
#pragma unroll
        for (int j = 0; j < 4; ++j) {
            int tt = t0 + j;
            bool in = (tt < src);
            bool r;
            if (y == YMAX) r = ((cs[j] == YMAX) && in) || (tt == src - 1);
            else           r = (cs[j] == y) && in;
            vv[j] = r ? 1.0f : 0.0f;
        }
    }
    *(float4*)(out + 32 + (size_t)b * TM + (size_t)y * XMAX + t0) = v;
}

// ---------------------------------------------------------------------------
extern "C" void kernel_launch(void* const* d_in, const int* in_sizes, int n_in,
                              void* d_out, int out_size)
{
    const float* ctc      = (const float*)d_in[0];
    // d_in[1] = src_mask (bool) — derivable from src_size, unused
    const int*   src_size = (const int*)d_in[2];
    const int*   ys       = (const int*)d_in[3];
    const int*   ylens    = (const int*)d_in[4];
    const int*   blank_p  = (n_in >= 6) ? (const int*)d_in[5] : nullptr;
    float*       out      = (float*)d_out;

    dim3 gg(XMAX / 8, BS);
    gather_kernel<<<gg, 288>>>(ctc, ys, src_size, blank_p);

    size_t smbytes = 131072            // bp bit-pairs
                   + 260 * 2           // path tokens
                   + 1024 * 2          // sal (state per frame)
                   + 288 * 4;          // final alpha
    cudaFuncSetAttribute(dp_kernel, cudaFuncAttributeMaxDynamicSharedMemorySize, (int)smbytes);
    dp_kernel<<<BS, 32, smbytes>>>(src_size, ys, ylens, blank_p, out);

    mask_kernel<<<BS * (YMAX + 1), XMAX / 4>>>(src_size, out);
}